// round 1
// baseline (speedup 1.0000x reference)
#include <cuda_runtime.h>
#include <math.h>

// ---------------- scratch (static __device__, no allocation) ----------------
#define Bn 8
#define Cn 64
#define Nn 4096   // 64*64
__device__ float g_featBC[Bn*16*Nn];     // rows 0-7: feat_b, 8-15: feat_c
__device__ float g_featD [Bn*Cn*Nn];
__device__ float g_x1    [Bn*Cn*Nn];     // after PAM residual
__device__ float g_gram  [32*Bn*Cn*Cn];  // split-K partials
__device__ float g_Pmat  [Bn*Cn*Cn];
__device__ float g_x2    [Bn*Cn*Nn];     // after CAM residual
__device__ float g_conv  [Bn*128*Nn];    // conv3x3 output (+bias)
__device__ float g_bnscale[128];
__device__ float g_bnshift[128];

// ---------------- f32x2 packed helpers ----------------
__device__ __forceinline__ unsigned long long pk2(float a, float b) {
    unsigned long long r;
    asm("mov.b64 %0, {%1, %2};" : "=l"(r) : "f"(a), "f"(b));
    return r;
}
__device__ __forceinline__ unsigned long long ffma2(unsigned long long a, unsigned long long b, unsigned long long c) {
    unsigned long long d;
    asm("fma.rn.f32x2 %0, %1, %2, %3;" : "=l"(d) : "l"(a), "l"(b), "l"(c));
    return d;
}
__device__ __forceinline__ unsigned long long mul2(unsigned long long a, unsigned long long b) {
    unsigned long long r;
    asm("mul.rn.f32x2 %0, %1, %2;" : "=l"(r) : "l"(a), "l"(b));
    return r;
}
__device__ __forceinline__ void unpk(unsigned long long v, float& lo, float& hi) {
    asm("mov.b64 {%0, %1}, %2;" : "=f"(lo), "=f"(hi) : "l"(v));
}

// ============ K1: fused 1x1 convs -> feat_b, feat_c, feat_d ============
__global__ __launch_bounds__(256) void k1_proj(
    const float* __restrict__ x,
    const float* __restrict__ wb, const float* __restrict__ bb,
    const float* __restrict__ wc, const float* __restrict__ bc,
    const float* __restrict__ wd, const float* __restrict__ bd)
{
    __shared__ __align__(16) float Ws[80*64];
    __shared__ float Bs[80];
    int t = threadIdx.x;
    for (int i = t; i < 512;  i += 256) Ws[i]        = wb[i];
    for (int i = t; i < 512;  i += 256) Ws[512 + i]  = wc[i];
    for (int i = t; i < 4096; i += 256) Ws[1024 + i] = wd[i];
    if (t < 8)        Bs[t] = bb[t];
    else if (t < 16)  Bs[t] = bc[t - 8];
    else if (t < 80)  Bs[t] = bd[t - 16];
    __syncthreads();

    int gid = blockIdx.x * 256 + t;
    int b = gid >> 12, p = gid & 4095;
    float xv[64];
    const float* xb = x + (size_t)b * Cn * Nn + p;
#pragma unroll
    for (int c = 0; c < 64; c++) xv[c] = xb[c * Nn];

    for (int o = 0; o < 80; o++) {
        float acc = Bs[o];
        const float4* wr = (const float4*)&Ws[o * 64];
#pragma unroll
        for (int c4 = 0; c4 < 16; c4++) {
            float4 w4 = wr[c4];
            acc += w4.x * xv[c4*4] + w4.y * xv[c4*4+1] + w4.z * xv[c4*4+2] + w4.w * xv[c4*4+3];
        }
        if (o < 16) g_featBC[((size_t)b * 16 + o) * Nn + p] = acc;
        else        g_featD [((size_t)b * Cn + (o - 16)) * Nn + p] = acc;
    }
}

// ============ K2: PAM flash attention + alpha residual ============
// block: (qt, b); 128 threads; 64 queries/block; m-chunks of 64
#define NQ 64
#define MC 64
#define VST 66   // even stride: 8B-aligned f32x2 + conflict-free (bank diff 2 per channel)
__global__ __launch_bounds__(128, 4) void k2_pam(
    const float* __restrict__ x, const float* __restrict__ alpha_p)
{
    __shared__ __align__(16) float Qs[NQ * 8];
    __shared__ __align__(16) float Ks[MC * 8];     // [m][c8]
    __shared__ __align__(16) float Vs[64 * VST];   // [c][m]
    __shared__ __align__(16) float Ps[NQ * VST];   // scores -> probs
    __shared__ float mrun[NQ], lrun[NQ], sscale[NQ];

    int b = blockIdx.y, q0 = blockIdx.x * NQ;
    int t = threadIdx.x;
    const float* featB = g_featBC + (size_t)b * 16 * Nn;
    const float* featC = featB + 8 * Nn;
    const float* featD = g_featD + (size_t)b * Cn * Nn;

    for (int idx = t; idx < NQ * 8; idx += 128) {
        int c8 = idx >> 6, q = idx & 63;
        Qs[q * 8 + c8] = featB[c8 * Nn + q0 + q];
    }
    if (t < NQ) { mrun[t] = -INFINITY; lrun[t] = 0.f; }

    int qg = t >> 3;      // 0..15 -> queries qg*4 + j
    int cg = t & 7;       // channels c = i*8 + cg
    unsigned long long acc[4][8];
#pragma unroll
    for (int j = 0; j < 4; j++)
#pragma unroll
        for (int i = 0; i < 8; i++) acc[j][i] = 0ull;

    for (int mc = 0; mc < Nn / MC; mc++) {
        int M0 = mc * MC;
        for (int idx = t; idx < MC * 8; idx += 128) {
            int c8 = idx >> 6, m = idx & 63;
            Ks[m * 8 + c8] = featC[c8 * Nn + M0 + m];
        }
        for (int idx = t; idx < 64 * MC; idx += 128) {
            int c = idx >> 6, m = idx & 63;
            Vs[c * VST + m] = featD[c * Nn + M0 + m];
        }
        __syncthreads();

        // scores: each thread one query, 32 m values
        {
            int q = t & 63, mb = (t >> 6) * 32;
            float4 qa = *(const float4*)&Qs[q * 8];
            float4 qb = *(const float4*)&Qs[q * 8 + 4];
#pragma unroll 8
            for (int mm = 0; mm < 32; mm++) {
                int m = mb + mm;
                float4 ka = *(const float4*)&Ks[m * 8];
                float4 kb = *(const float4*)&Ks[m * 8 + 4];
                float s = qa.x*ka.x + qa.y*ka.y + qa.z*ka.z + qa.w*ka.w
                        + qb.x*kb.x + qb.y*kb.y + qb.z*kb.z + qb.w*kb.w;
                Ps[q * VST + m] = s;
            }
        }
        __syncthreads();

        // online softmax, one thread per query
        if (t < NQ) {
            int q = t;
            float cmax = -INFINITY;
#pragma unroll 8
            for (int m = 0; m < MC; m++) cmax = fmaxf(cmax, Ps[q * VST + m]);
            float nm = fmaxf(mrun[q], cmax);
            float sc = __expf(mrun[q] - nm);
            float sum = 0.f;
#pragma unroll 8
            for (int m = 0; m < MC; m++) {
                float p = __expf(Ps[q * VST + m] - nm);
                Ps[q * VST + m] = p;
                sum += p;
            }
            lrun[q] = lrun[q] * sc + sum;
            mrun[q] = nm;
            sscale[q] = sc;
        }
        __syncthreads();

        // rescale + accumulate with packed f32x2
        {
            unsigned long long scp[4];
#pragma unroll
            for (int j = 0; j < 4; j++) {
                float s = sscale[qg * 4 + j];
                scp[j] = pk2(s, s);
            }
#pragma unroll
            for (int j = 0; j < 4; j++)
#pragma unroll
                for (int i = 0; i < 8; i++) acc[j][i] = mul2(acc[j][i], scp[j]);

#pragma unroll 4
            for (int m = 0; m < MC; m += 2) {
                unsigned long long p2[4], v2[8];
#pragma unroll
                for (int j = 0; j < 4; j++)
                    p2[j] = *(const unsigned long long*)&Ps[(qg * 4 + j) * VST + m];
#pragma unroll
                for (int i = 0; i < 8; i++)
                    v2[i] = *(const unsigned long long*)&Vs[(i * 8 + cg) * VST + m];
#pragma unroll
                for (int j = 0; j < 4; j++)
#pragma unroll
                    for (int i = 0; i < 8; i++)
                        acc[j][i] = ffma2(v2[i], p2[j], acc[j][i]);
            }
        }
        __syncthreads();
    }

    float alpha = *alpha_p;
#pragma unroll
    for (int j = 0; j < 4; j++) {
        int q = q0 + qg * 4 + j;
        float invl = 1.f / lrun[qg * 4 + j];
#pragma unroll
        for (int i = 0; i < 8; i++) {
            int c = i * 8 + cg;
            float lo, hi;
            unpk(acc[j][i], lo, hi);
            float fe = (lo + hi) * invl;
            size_t off = ((size_t)b * Cn + c) * Nn + q;
            g_x1[off] = alpha * fe + x[off];
        }
    }
}

// ============ K3a: CAM Gram partials (split over N) ============
__global__ __launch_bounds__(256) void k3a_gram()
{
    __shared__ float Xs[64 * 129];
    int b = blockIdx.y, ns = blockIdx.x;
    int n0 = ns * 128;
    int t = threadIdx.x;
    const float* x1b = g_x1 + (size_t)b * Cn * Nn;
    for (int idx = t; idx < 64 * 128; idx += 256) {
        int c = idx >> 7, n = idx & 127;
        Xs[c * 129 + n] = x1b[c * Nn + n0 + n];
    }
    __syncthreads();
    int c0 = t & 63, dg = t >> 6;  // dg 0..3
    float acc[16];
#pragma unroll
    for (int k = 0; k < 16; k++) acc[k] = 0.f;
    for (int n = 0; n < 128; n++) {
        float xc = Xs[c0 * 129 + n];
#pragma unroll
        for (int k = 0; k < 16; k++) acc[k] += xc * Xs[(dg * 16 + k) * 129 + n];
    }
#pragma unroll
    for (int k = 0; k < 16; k++)
        g_gram[(((size_t)ns * Bn + b) * Cn + c0) * Cn + dg * 16 + k] = acc[k];
}

// ============ K3b: CAM softmax(max-att) ============
__global__ __launch_bounds__(64) void k3b_soft()
{
    int c = blockIdx.x, b = blockIdx.y, d = threadIdx.x;
    float v = 0.f;
    for (int ns = 0; ns < 32; ns++)
        v += g_gram[(((size_t)ns * Bn + b) * Cn + c) * Cn + d];
    __shared__ float vals[64], pbuf[64];
    vals[d] = v;
    __syncthreads();
    float M = -INFINITY, mn = INFINITY;
    for (int i = 0; i < 64; i++) { M = fmaxf(M, vals[i]); mn = fminf(mn, vals[i]); }
    // softmax(M - v) == exp(mn - v)/sum
    float p = __expf(mn - v);
    pbuf[d] = p;
    __syncthreads();
    float S = 0.f;
    for (int i = 0; i < 64; i++) S += pbuf[i];
    g_Pmat[((size_t)b * Cn + c) * Cn + d] = p / S;
}

// ============ K3c: CAM apply + beta residual ============
__global__ __launch_bounds__(256) void k3c_apply(const float* __restrict__ beta_p)
{
    __shared__ __align__(16) float Pm[4096];
    int b = blockIdx.y;
    int t = threadIdx.x;
    for (int i = t; i < 4096; i += 256) Pm[i] = g_Pmat[(size_t)b * 4096 + i];
    __syncthreads();
    int p = blockIdx.x * 256 + t;
    float xv[64];
    const float* x1b = g_x1 + (size_t)b * Cn * Nn + p;
#pragma unroll
    for (int c = 0; c < 64; c++) xv[c] = x1b[c * Nn];
    float beta = *beta_p;
    for (int c = 0; c < 64; c++) {
        float acc = 0.f;
        const float4* pr = (const float4*)&Pm[c * 64];
#pragma unroll
        for (int d4 = 0; d4 < 16; d4++) {
            float4 w4 = pr[d4];
            acc += w4.x * xv[d4*4] + w4.y * xv[d4*4+1] + w4.z * xv[d4*4+2] + w4.w * xv[d4*4+3];
        }
        g_x2[((size_t)b * Cn + c) * Nn + p] = beta * acc + xv[c];
    }
}

// ============ K4: conv3x3 (pad 1) -> g_conv (with bias) ============
__global__ __launch_bounds__(256) void k4_conv(
    const float* __restrict__ w, const float* __restrict__ bias)
{
    __shared__ float In[8][18][18];
    __shared__ __align__(16) float Ws[32][8][12];
    int b = blockIdx.z, ocg = blockIdx.y, tile = blockIdx.x;
    int ty0 = (tile >> 2) * 16, tx0 = (tile & 3) * 16;
    int t = threadIdx.x;
    int lx = t & 15, ly = t >> 4;
    float acc[32];
#pragma unroll
    for (int oc = 0; oc < 32; oc++) acc[oc] = bias[ocg * 32 + oc];
    const float* xin = g_x2 + (size_t)b * Cn * Nn;

    for (int icc = 0; icc < 8; icc++) {
        __syncthreads();
        for (int idx = t; idx < 2592; idx += 256) {
            int ic = idx / 324;
            int rem = idx - ic * 324;
            int r = rem / 18, cc = rem - r * 18;
            int y = ty0 + r - 1, xx = tx0 + cc - 1;
            float v = 0.f;
            if (y >= 0 && y < 64 && xx >= 0 && xx < 64)
                v = xin[(icc * 8 + ic) * Nn + y * 64 + xx];
            In[ic][r][cc] = v;
        }
        for (int idx = t; idx < 32 * 8 * 9; idx += 256) {
            int oc = idx / 72;
            int rem = idx - oc * 72;
            int ic = rem / 9, k = rem - ic * 9;
            Ws[oc][ic][k] = w[(((size_t)(ocg * 32 + oc)) * 64 + icc * 8 + ic) * 9 + k];
        }
        __syncthreads();
#pragma unroll
        for (int ic = 0; ic < 8; ic++) {
            float i0 = In[ic][ly    ][lx], i1 = In[ic][ly    ][lx+1], i2 = In[ic][ly    ][lx+2];
            float i3 = In[ic][ly + 1][lx], i4 = In[ic][ly + 1][lx+1], i5 = In[ic][ly + 1][lx+2];
            float i6 = In[ic][ly + 2][lx], i7 = In[ic][ly + 2][lx+1], i8 = In[ic][ly + 2][lx+2];
#pragma unroll
            for (int oc = 0; oc < 32; oc++) {
                float4 wa = *(const float4*)&Ws[oc][ic][0];
                float4 wb = *(const float4*)&Ws[oc][ic][4];
                float w8 = Ws[oc][ic][8];
                acc[oc] += i0*wa.x + i1*wa.y + i2*wa.z + i3*wa.w
                         + i4*wb.x + i5*wb.y + i6*wb.z + i7*wb.w + i8*w8;
            }
        }
    }
#pragma unroll
    for (int oc = 0; oc < 32; oc++)
        g_conv[((size_t)b * 128 + ocg * 32 + oc) * Nn + (ty0 + ly) * 64 + tx0 + lx] = acc[oc];
}

// ============ K5: BN batch stats (deterministic, 1 block/channel) ============
__global__ __launch_bounds__(256) void k5_bnstats(
    const float* __restrict__ gamma, const float* __restrict__ betab)
{
    int c = blockIdx.x, t = threadIdx.x;
    float s = 0.f, s2 = 0.f;
    for (int i = t; i < Bn * Nn; i += 256) {
        int bb = i >> 12, p = i & 4095;
        float v = g_conv[((size_t)bb * 128 + c) * Nn + p];
        s += v; s2 += v * v;
    }
    __shared__ float rs[256], rq[256];
    rs[t] = s; rq[t] = s2;
    __syncthreads();
    for (int o = 128; o > 0; o >>= 1) {
        if (t < o) { rs[t] += rs[t + o]; rq[t] += rq[t + o]; }
        __syncthreads();
    }
    if (t == 0) {
        float mean = rs[0] / 32768.f;
        float var = rq[0] / 32768.f - mean * mean;
        float sc = gamma[c] * rsqrtf(var + 1e-5f);
        g_bnscale[c] = sc;
        g_bnshift[c] = betab[c] - mean * sc;
    }
}

// ============ K6: BN apply + ReLU + maxpool(2,2, h-pad (1,1)) ============
__global__ __launch_bounds__(256) void k6_pool(float* __restrict__ out)
{
    int idx = blockIdx.x * 256 + threadIdx.x;
    const int TOT = Bn * 128 * 33 * 32;
    if (idx >= TOT) return;
    int ow = idx & 31;
    int rest = idx >> 5;
    int oh = rest % 33; rest /= 33;
    int c = rest & 127;
    int b = rest >> 7;
    float sc = g_bnscale[c], sh = g_bnshift[c];
    const float* base = g_conv + ((size_t)b * 128 + c) * Nn;
    int r0 = 2 * oh - 1, r1 = 2 * oh;
    int x0 = 2 * ow;
    float m = -INFINITY;
    if (r0 >= 0 && r0 < 64) {
        m = fmaxf(m, fmaxf(base[r0 * 64 + x0] * sc + sh, 0.f));
        m = fmaxf(m, fmaxf(base[r0 * 64 + x0 + 1] * sc + sh, 0.f));
    }
    if (r1 < 64) {
        m = fmaxf(m, fmaxf(base[r1 * 64 + x0] * sc + sh, 0.f));
        m = fmaxf(m, fmaxf(base[r1 * 64 + x0 + 1] * sc + sh, 0.f));
    }
    out[idx] = m;
}

// ---------------- launch ----------------
extern "C" void kernel_launch(void* const* d_in, const int* in_sizes, int n_in,
                              void* d_out, int out_size)
{
    const float* x       = (const float*)d_in[0];
    const float* conv_bw = (const float*)d_in[1];
    const float* conv_bb = (const float*)d_in[2];
    const float* conv_cw = (const float*)d_in[3];
    const float* conv_cb = (const float*)d_in[4];
    const float* conv_dw = (const float*)d_in[5];
    const float* conv_db = (const float*)d_in[6];
    const float* alpha   = (const float*)d_in[7];
    const float* beta    = (const float*)d_in[8];
    const float* conv_w  = (const float*)d_in[9];
    const float* conv_b  = (const float*)d_in[10];
    const float* bn_g    = (const float*)d_in[11];
    const float* bn_b    = (const float*)d_in[12];
    float* out = (float*)d_out;

    k1_proj<<<128, 256>>>(x, conv_bw, conv_bb, conv_cw, conv_cb, conv_dw, conv_db);
    k2_pam<<<dim3(Nn / NQ, Bn), 128>>>(x, alpha);
    k3a_gram<<<dim3(32, Bn), 256>>>();
    k3b_soft<<<dim3(64, Bn), 64>>>();
    k3c_apply<<<dim3(16, Bn), 256>>>(beta);
    k4_conv<<<dim3(16, 4, Bn), 256>>>(conv_w, conv_b);
    k5_bnstats<<<128, 256>>>(bn_g, bn_b);
    k6_pool<<<4224, 256>>>(out);
}

// round 5
// speedup vs baseline: 1.8720x; 1.8720x over previous
#include <cuda_runtime.h>
#include <cuda_bf16.h>
#include <math.h>
#include <stdint.h>

// ---------------- scratch (static __device__, no allocation) ----------------
#define Bn 8
#define Cn 64
#define Nn 4096   // 64*64
__device__ __nv_bfloat16 g_featBT[Bn*Nn*8];    // [b][n][c8]  (16B rows)
__device__ __nv_bfloat16 g_featCb[Bn*8*Nn];    // [b][c8][n]
__device__ __nv_bfloat16 g_featDT[Bn*Nn*64];   // [b][n][c]   (128B rows)
__device__ float g_x1    [Bn*Cn*Nn];     // after PAM residual
__device__ float g_gram  [32*Bn*Cn*Cn];  // split-K partials
__device__ float g_Pmat  [Bn*Cn*Cn];
__device__ float g_x2    [Bn*Cn*Nn];     // after CAM residual
__device__ float g_conv  [Bn*128*Nn];    // conv3x3 output (+bias)
__device__ float g_bnscale[128];
__device__ float g_bnshift[128];

// ---------------- mma / ldmatrix helpers ----------------
__device__ __forceinline__ uint32_t sptr(const void* p) {
    return (uint32_t)__cvta_generic_to_shared(p);
}
__device__ __forceinline__ void ldm_x4(uint32_t* r, uint32_t addr) {
    asm volatile("ldmatrix.sync.aligned.m8n8.x4.shared.b16 {%0,%1,%2,%3}, [%4];"
        : "=r"(r[0]), "=r"(r[1]), "=r"(r[2]), "=r"(r[3]) : "r"(addr));
}
__device__ __forceinline__ void ldm_x4_t(uint32_t* r, uint32_t addr) {
    asm volatile("ldmatrix.sync.aligned.m8n8.x4.trans.shared.b16 {%0,%1,%2,%3}, [%4];"
        : "=r"(r[0]), "=r"(r[1]), "=r"(r[2]), "=r"(r[3]) : "r"(addr));
}
__device__ __forceinline__ void mma_bf16(float* d, const uint32_t* a, uint32_t b0, uint32_t b1) {
    asm volatile(
        "mma.sync.aligned.m16n8k16.row.col.f32.bf16.bf16.f32 "
        "{%0,%1,%2,%3}, {%4,%5,%6,%7}, {%8,%9}, {%0,%1,%2,%3};"
        : "+f"(d[0]), "+f"(d[1]), "+f"(d[2]), "+f"(d[3])
        : "r"(a[0]), "r"(a[1]), "r"(a[2]), "r"(a[3]), "r"(b0), "r"(b1));
}
__device__ __forceinline__ uint32_t bf2u(float a, float b) {
    __nv_bfloat162 p = __floats2bfloat162_rn(a, b);
    return *(uint32_t*)&p;
}

// ============ K1: fused 1x1 convs -> bf16 operand layouts ============
__global__ __launch_bounds__(256) void k1_proj(
    const float* __restrict__ x,
    const float* __restrict__ wb, const float* __restrict__ bb,
    const float* __restrict__ wc, const float* __restrict__ bc,
    const float* __restrict__ wd, const float* __restrict__ bd)
{
    __shared__ __align__(16) float Ws[80*64];
    __shared__ float Bs[80];
    int t = threadIdx.x;
    for (int i = t; i < 512;  i += 256) Ws[i]        = wb[i];
    for (int i = t; i < 512;  i += 256) Ws[512 + i]  = wc[i];
    for (int i = t; i < 4096; i += 256) Ws[1024 + i] = wd[i];
    if (t < 8)        Bs[t] = bb[t];
    else if (t < 16)  Bs[t] = bc[t - 8];
    else if (t < 80)  Bs[t] = bd[t - 16];
    __syncthreads();

    int gid = blockIdx.x * 256 + t;
    int b = gid >> 12, p = gid & 4095;
    float xv[64];
    const float* xb = x + (size_t)b * Cn * Nn + p;
#pragma unroll
    for (int c = 0; c < 64; c++) xv[c] = xb[c * Nn];

    float accT[8];
    for (int o = 0; o < 80; o++) {
        float acc = Bs[o];
        const float4* wr = (const float4*)&Ws[o * 64];
#pragma unroll
        for (int c4 = 0; c4 < 16; c4++) {
            float4 w4 = wr[c4];
            acc += w4.x * xv[c4*4] + w4.y * xv[c4*4+1] + w4.z * xv[c4*4+2] + w4.w * xv[c4*4+3];
        }
        if (o < 8) {
            accT[o] = acc;
            if (o == 7) {
                uint4 v;
                v.x = bf2u(accT[0], accT[1]); v.y = bf2u(accT[2], accT[3]);
                v.z = bf2u(accT[4], accT[5]); v.w = bf2u(accT[6], accT[7]);
                *(uint4*)&g_featBT[((size_t)b * Nn + p) * 8] = v;
            }
        } else if (o < 16) {
            g_featCb[((size_t)b * 8 + (o - 8)) * Nn + p] = __float2bfloat16(acc);
        } else {
            int c = o - 16;
            accT[c & 7] = acc;
            if ((c & 7) == 7) {
                uint4 v;
                v.x = bf2u(accT[0], accT[1]); v.y = bf2u(accT[2], accT[3]);
                v.z = bf2u(accT[4], accT[5]); v.w = bf2u(accT[6], accT[7]);
                *(uint4*)&g_featDT[((size_t)b * Nn + p) * 64 + (c - 7)] = v;
            }
        }
    }
}

// ============ K2: PAM flash attention via bf16 mma.sync ============
#define KST2 72
#define VST2 72
#define PST2 72
#define SST  65
__global__ __launch_bounds__(128, 4) void k2_pam(
    const float* __restrict__ x, const float* __restrict__ alpha_p)
{
    __shared__ __align__(16) __nv_bfloat16 Qb[64*16];
    __shared__ __align__(16) __nv_bfloat16 Kb[16*KST2];
    __shared__ __align__(16) __nv_bfloat16 Vb[64*VST2];
    __shared__ __align__(16) float Sf[64*SST];
    __shared__ __align__(16) __nv_bfloat16 Pb[64*PST2];
    __shared__ float mrun[64], lrun[64], sscale[64];
    __shared__ float red1[2][64], red2[2][64];

    int b = blockIdx.y, q0 = blockIdx.x * 64;
    int t = threadIdx.x, lane = t & 31, warp = t >> 5;
    int qbase = warp * 16;

    const __nv_bfloat16* featB = g_featBT + (size_t)b * Nn * 8;
    const __nv_bfloat16* featC = g_featCb + (size_t)b * 8 * Nn;
    const __nv_bfloat16* featD = g_featDT + (size_t)b * Nn * 64;

    // init: Q tile (cols 8..15 zero), Kb all-zero (rows 8..15 stay zero), stats
    {
        int q = t >> 1;
        if (t & 1) {
            uint4 z = {0,0,0,0};
            *(uint4*)&Qb[q * 16 + 8] = z;
        } else {
            *(uint4*)&Qb[q * 16] = *(const uint4*)&featB[(size_t)(q0 + q) * 8];
        }
        for (int i = t; i < 16 * KST2 / 8; i += 128) {
            uint4 z = {0,0,0,0};
            *(uint4*)&Kb[i * 8] = z;
        }
        if (t < 64) { mrun[t] = -INFINITY; lrun[t] = 0.f; }
    }
    __syncthreads();

    // per-warp Q fragment (A, 16x16)
    uint32_t qa[4];
    {
        int r = lane & 15, ch = (lane >> 4) * 8;
        ldm_x4(qa, sptr(&Qb[(qbase + r) * 16 + ch]));
    }

    float acc[8][4];
#pragma unroll
    for (int n = 0; n < 8; n++)
#pragma unroll
        for (int j = 0; j < 4; j++) acc[n][j] = 0.f;

    for (int mc = 0; mc < 64; mc++) {
        int M0 = mc * 64;
        // load K chunk rows 0-7 (bf16 pairs)
        for (int i = t; i < 256; i += 128) {
            int c = i >> 5, m2 = i & 31;
            *(uint32_t*)&Kb[c * KST2 + 2 * m2] =
                *(const uint32_t*)&featC[(size_t)c * Nn + M0 + 2 * m2];
        }
        // load V chunk [m][c]: 64 rows x 8 uint4 (8 bf16 each) = full 64 cols
        for (int i = t; i < 512; i += 128) {
            int m = i >> 3, cq = i & 7;
            *(uint4*)&Vb[m * VST2 + cq * 8] =
                *(const uint4*)&featD[(size_t)(M0 + m) * 64 + cq * 8];
        }
        __syncthreads();

        // ---- scores: S[q][m] = Q·K, one k-tile (K=16, upper 8 zero) ----
        {
            int r = lane & 7, sel = lane >> 3;
            int row = lane >> 2, col2 = (lane & 3) * 2;
#pragma unroll
            for (int nt2 = 0; nt2 < 4; nt2++) {
                uint32_t kb[4];
                ldm_x4_t(kb, sptr(&Kb[(r + (sel & 1) * 8) * KST2 + nt2 * 16 + (sel >> 1) * 8]));
                float d0[4] = {0,0,0,0}, d1[4] = {0,0,0,0};
                mma_bf16(d0, qa, kb[0], kb[1]);
                mma_bf16(d1, qa, kb[2], kb[3]);
                int mA = nt2 * 16 + col2, mB = mA + 8;
                Sf[(qbase + row) * SST + mA]     = d0[0];
                Sf[(qbase + row) * SST + mA + 1] = d0[1];
                Sf[(qbase + row + 8) * SST + mA]     = d0[2];
                Sf[(qbase + row + 8) * SST + mA + 1] = d0[3];
                Sf[(qbase + row) * SST + mB]     = d1[0];
                Sf[(qbase + row) * SST + mB + 1] = d1[1];
                Sf[(qbase + row + 8) * SST + mB]     = d1[2];
                Sf[(qbase + row + 8) * SST + mB + 1] = d1[3];
            }
        }
        __syncthreads();

        // ---- online softmax: 2 threads per query ----
        {
            int q = t & 63, h = t >> 6;
            const float* srow = &Sf[q * SST + h * 32];
            float cmax = -INFINITY;
#pragma unroll 8
            for (int m = 0; m < 32; m++) cmax = fmaxf(cmax, srow[m]);
            red1[h][q] = cmax;
            __syncthreads();
            float nm = fmaxf(mrun[q], fmaxf(red1[0][q], red1[1][q]));
            float sum = 0.f;
            __nv_bfloat162* prow = (__nv_bfloat162*)&Pb[q * PST2 + h * 32];
#pragma unroll 8
            for (int m2 = 0; m2 < 16; m2++) {
                float p0 = __expf(srow[2 * m2] - nm);
                float p1 = __expf(srow[2 * m2 + 1] - nm);
                prow[m2] = __floats2bfloat162_rn(p0, p1);
                sum += p0 + p1;
            }
            red2[h][q] = sum;
            __syncthreads();
            if (h == 0) {
                float sc = __expf(mrun[q] - nm);
                lrun[q] = lrun[q] * sc + red2[0][q] + red2[1][q];
                mrun[q] = nm;
                sscale[q] = sc;
            }
        }
        __syncthreads();

        // ---- P·V accumulate ----
        {
            float s0 = sscale[qbase + (lane >> 2)];
            float s1 = sscale[qbase + (lane >> 2) + 8];
#pragma unroll
            for (int n = 0; n < 8; n++) {
                acc[n][0] *= s0; acc[n][1] *= s0;
                acc[n][2] *= s1; acc[n][3] *= s1;
            }
            uint32_t pa[4][4];
            {
                int r = lane & 15, ch = (lane >> 4) * 8;
#pragma unroll
                for (int kt = 0; kt < 4; kt++)
                    ldm_x4(pa[kt], sptr(&Pb[(qbase + r) * PST2 + kt * 16 + ch]));
            }
            int r = lane & 7, sel = lane >> 3;
#pragma unroll
            for (int kt = 0; kt < 4; kt++) {
#pragma unroll
                for (int nt2 = 0; nt2 < 4; nt2++) {
                    uint32_t vb[4];
                    ldm_x4_t(vb, sptr(&Vb[(kt * 16 + r + (sel & 1) * 8) * VST2
                                          + nt2 * 16 + (sel >> 1) * 8]));
                    mma_bf16(acc[nt2 * 2],     pa[kt], vb[0], vb[1]);
                    mma_bf16(acc[nt2 * 2 + 1], pa[kt], vb[2], vb[3]);
                }
            }
        }
        __syncthreads();
    }

    // epilogue: normalize + alpha residual
    {
        float alpha = *alpha_p;
        int row = lane >> 2, col2 = (lane & 3) * 2;
        float il0 = 1.f / lrun[qbase + row];
        float il1 = 1.f / lrun[qbase + row + 8];
        int qA = q0 + qbase + row;
#pragma unroll
        for (int nt = 0; nt < 8; nt++) {
            int c = nt * 8 + col2;
            size_t o0 = ((size_t)b * Cn + c) * Nn + qA;
            g_x1[o0]          = alpha * acc[nt][0] * il0 + x[o0];
            g_x1[o0 + Nn]     = alpha * acc[nt][1] * il0 + x[o0 + Nn];
            g_x1[o0 + 8]      = alpha * acc[nt][2] * il1 + x[o0 + 8];
            g_x1[o0 + Nn + 8] = alpha * acc[nt][3] * il1 + x[o0 + Nn + 8];
        }
    }
}

// ============ K3a: CAM Gram partials (split over N) ============
__global__ __launch_bounds__(256) void k3a_gram()
{
    __shared__ float Xs[64 * 129];
    int b = blockIdx.y, ns = blockIdx.x;
    int n0 = ns * 128;
    int t = threadIdx.x;
    const float* x1b = g_x1 + (size_t)b * Cn * Nn;
    for (int idx = t; idx < 64 * 128; idx += 256) {
        int c = idx >> 7, n = idx & 127;
        Xs[c * 129 + n] = x1b[c * Nn + n0 + n];
    }
    __syncthreads();
    int c0 = t & 63, dg = t >> 6;
    float acc[16];
#pragma unroll
    for (int k = 0; k < 16; k++) acc[k] = 0.f;
    for (int n = 0; n < 128; n++) {
        float xc = Xs[c0 * 129 + n];
#pragma unroll
        for (int k = 0; k < 16; k++) acc[k] += xc * Xs[(dg * 16 + k) * 129 + n];
    }
#pragma unroll
    for (int k = 0; k < 16; k++)
        g_gram[(((size_t)ns * Bn + b) * Cn + c0) * Cn + dg * 16 + k] = acc[k];
}

// ============ K3b: CAM softmax(max-att) ============
__global__ __launch_bounds__(64) void k3b_soft()
{
    int c = blockIdx.x, b = blockIdx.y, d = threadIdx.x;
    float v = 0.f;
    for (int ns = 0; ns < 32; ns++)
        v += g_gram[(((size_t)ns * Bn + b) * Cn + c) * Cn + d];
    __shared__ float vals[64], pbuf[64];
    vals[d] = v;
    __syncthreads();
    float mn = INFINITY;
    for (int i = 0; i < 64; i++) mn = fminf(mn, vals[i]);
    float p = __expf(mn - v);
    pbuf[d] = p;
    __syncthreads();
    float S = 0.f;
    for (int i = 0; i < 64; i++) S += pbuf[i];
    g_Pmat[((size_t)b * Cn + c) * Cn + d] = p / S;
}

// ============ K3c: CAM apply + beta residual ============
__global__ __launch_bounds__(256) void k3c_apply(const float* __restrict__ beta_p)
{
    __shared__ __align__(16) float Pm[4096];
    int b = blockIdx.y;
    int t = threadIdx.x;
    for (int i = t; i < 4096; i += 256) Pm[i] = g_Pmat[(size_t)b * 4096 + i];
    __syncthreads();
    int p = blockIdx.x * 256 + t;
    float xv[64];
    const float* x1b = g_x1 + (size_t)b * Cn * Nn + p;
#pragma unroll
    for (int c = 0; c < 64; c++) xv[c] = x1b[c * Nn];
    float beta = *beta_p;
    for (int c = 0; c < 64; c++) {
        float acc = 0.f;
        const float4* pr = (const float4*)&Pm[c * 64];
#pragma unroll
        for (int d4 = 0; d4 < 16; d4++) {
            float4 w4 = pr[d4];
            acc += w4.x * xv[d4*4] + w4.y * xv[d4*4+1] + w4.z * xv[d4*4+2] + w4.w * xv[d4*4+3];
        }
        g_x2[((size_t)b * Cn + c) * Nn + p] = beta * acc + xv[c];
    }
}

// ============ K4: conv3x3 (pad 1) -> g_conv (with bias) ============
__global__ __launch_bounds__(256) void k4_conv(
    const float* __restrict__ w, const float* __restrict__ bias)
{
    __shared__ float In[8][18][18];
    __shared__ __align__(16) float Ws[32][8][12];
    int b = blockIdx.z, ocg = blockIdx.y, tile = blockIdx.x;
    int ty0 = (tile >> 2) * 16, tx0 = (tile & 3) * 16;
    int t = threadIdx.x;
    int lx = t & 15, ly = t >> 4;
    float acc[32];
#pragma unroll
    for (int oc = 0; oc < 32; oc++) acc[oc] = bias[ocg * 32 + oc];
    const float* xin = g_x2 + (size_t)b * Cn * Nn;

    for (int icc = 0; icc < 8; icc++) {
        __syncthreads();
        for (int idx = t; idx < 2592; idx += 256) {
            int ic = idx / 324;
            int rem = idx - ic * 324;
            int r = rem / 18, cc = rem - r * 18;
            int y = ty0 + r - 1, xx = tx0 + cc - 1;
            float v = 0.f;
            if (y >= 0 && y < 64 && xx >= 0 && xx < 64)
                v = xin[(icc * 8 + ic) * Nn + y * 64 + xx];
            In[ic][r][cc] = v;
        }
        for (int idx = t; idx < 32 * 8 * 9; idx += 256) {
            int oc = idx / 72;
            int rem = idx - oc * 72;
            int ic = rem / 9, k = rem - ic * 9;
            Ws[oc][ic][k] = w[(((size_t)(ocg * 32 + oc)) * 64 + icc * 8 + ic) * 9 + k];
        }
        __syncthreads();
#pragma unroll
        for (int ic = 0; ic < 8; ic++) {
            float i0 = In[ic][ly    ][lx], i1 = In[ic][ly    ][lx+1], i2 = In[ic][ly    ][lx+2];
            float i3 = In[ic][ly + 1][lx], i4 = In[ic][ly + 1][lx+1], i5 = In[ic][ly + 1][lx+2];
            float i6 = In[ic][ly + 2][lx], i7 = In[ic][ly + 2][lx+1], i8 = In[ic][ly + 2][lx+2];
#pragma unroll
            for (int oc = 0; oc < 32; oc++) {
                float4 wa = *(const float4*)&Ws[oc][ic][0];
                float4 wb = *(const float4*)&Ws[oc][ic][4];
                float w8 = Ws[oc][ic][8];
                acc[oc] += i0*wa.x + i1*wa.y + i2*wa.z + i3*wa.w
                         + i4*wb.x + i5*wb.y + i6*wb.z + i7*wb.w + i8*w8;
            }
        }
    }
#pragma unroll
    for (int oc = 0; oc < 32; oc++)
        g_conv[((size_t)b * 128 + ocg * 32 + oc) * Nn + (ty0 + ly) * 64 + tx0 + lx] = acc[oc];
}

// ============ K5: BN batch stats (deterministic, 1 block/channel) ============
__global__ __launch_bounds__(256) void k5_bnstats(
    const float* __restrict__ gamma, const float* __restrict__ betab)
{
    int c = blockIdx.x, t = threadIdx.x;
    float s = 0.f, s2 = 0.f;
    for (int i = t; i < Bn * Nn; i += 256) {
        int bb = i >> 12, p = i & 4095;
        float v = g_conv[((size_t)bb * 128 + c) * Nn + p];
        s += v; s2 += v * v;
    }
    __shared__ float rs[256], rq[256];
    rs[t] = s; rq[t] = s2;
    __syncthreads();
    for (int o = 128; o > 0; o >>= 1) {
        if (t < o) { rs[t] += rs[t + o]; rq[t] += rq[t + o]; }
        __syncthreads();
    }
    if (t == 0) {
        float mean = rs[0] / 32768.f;
        float var = rq[0] / 32768.f - mean * mean;
        float sc = gamma[c] * rsqrtf(var + 1e-5f);
        g_bnscale[c] = sc;
        g_bnshift[c] = betab[c] - mean * sc;
    }
}

// ============ K6: BN apply + ReLU + maxpool(2,2, h-pad (1,1)) ============
__global__ __launch_bounds__(256) void k6_pool(float* __restrict__ out)
{
    int idx = blockIdx.x * 256 + threadIdx.x;
    const int TOT = Bn * 128 * 33 * 32;
    if (idx >= TOT) return;
    int ow = idx & 31;
    int rest = idx >> 5;
    int oh = rest % 33; rest /= 33;
    int c = rest & 127;
    int b = rest >> 7;
    float sc = g_bnscale[c], sh = g_bnshift[c];
    const float* base = g_conv + ((size_t)b * 128 + c) * Nn;
    int r0 = 2 * oh - 1, r1 = 2 * oh;
    int x0 = 2 * ow;
    float m = -INFINITY;
    if (r0 >= 0 && r0 < 64) {
        m = fmaxf(m, fmaxf(base[r0 * 64 + x0] * sc + sh, 0.f));
        m = fmaxf(m, fmaxf(base[r0 * 64 + x0 + 1] * sc + sh, 0.f));
    }
    if (r1 < 64) {
        m = fmaxf(m, fmaxf(base[r1 * 64 + x0] * sc + sh, 0.f));
        m = fmaxf(m, fmaxf(base[r1 * 64 + x0 + 1] * sc + sh, 0.f));
    }
    out[idx] = m;
}

// ---------------- launch ----------------
extern "C" void kernel_launch(void* const* d_in, const int* in_sizes, int n_in,
                              void* d_out, int out_size)
{
    const float* x       = (const float*)d_in[0];
    const float* conv_bw = (const float*)d_in[1];
    const float* conv_bb = (const float*)d_in[2];
    const float* conv_cw = (const float*)d_in[3];
    const float* conv_cb = (const float*)d_in[4];
    const float* conv_dw = (const float*)d_in[5];
    const float* conv_db = (const float*)d_in[6];
    const float* alpha   = (const float*)d_in[7];
    const float* beta    = (const float*)d_in[8];
    const float* conv_w  = (const float*)d_in[9];
    const float* conv_b  = (const float*)d_in[10];
    const float* bn_g    = (const float*)d_in[11];
    const float* bn_b    = (const float*)d_in[12];
    float* out = (float*)d_out;

    k1_proj<<<128, 256>>>(x, conv_bw, conv_bb, conv_cw, conv_cb, conv_dw, conv_db);
    k2_pam<<<dim3(64, Bn), 128>>>(x, alpha);
    k3a_gram<<<dim3(32, Bn), 256>>>();
    k3b_soft<<<dim3(64, Bn), 64>>>();
    k3c_apply<<<dim3(16, Bn), 256>>>(beta);
    k4_conv<<<dim3(16, 4, Bn), 256>>>(conv_w, conv_b);
    k5_bnstats<<<128, 256>>>(bn_g, bn_b);
    k6_pool<<<4224, 256>>>(out);
}

// round 7
// speedup vs baseline: 2.2120x; 1.1816x over previous
#include <cuda_runtime.h>
#include <cuda_bf16.h>
#include <math.h>
#include <stdint.h>

// ---------------- scratch (static __device__, no allocation) ----------------
#define Bn 8
#define Cn 64
#define Nn 4096   // 64*64
__device__ __nv_bfloat16 g_featBT[Bn*Nn*8];    // [b][n][c8]  (16B rows)
__device__ __nv_bfloat16 g_featCb[Bn*8*Nn];    // [b][c8][n]
__device__ __nv_bfloat16 g_featDT[Bn*Nn*64];   // [b][n][c]   (128B rows)
__device__ float g_x1    [Bn*Cn*Nn];     // after PAM residual
__device__ float g_gram  [32*Bn*Cn*Cn];  // split-K partials
__device__ float g_Pmat  [Bn*Cn*Cn];
__device__ float g_x2    [Bn*Cn*Nn];     // after CAM residual
__device__ float g_conv  [Bn*128*Nn];    // conv3x3 output (+bias)
__device__ float g_bnscale[128];
__device__ float g_bnshift[128];

// ---------------- mma / ldmatrix helpers ----------------
__device__ __forceinline__ uint32_t sptr(const void* p) {
    return (uint32_t)__cvta_generic_to_shared(p);
}
__device__ __forceinline__ void ldm_x4(uint32_t* r, uint32_t addr) {
    asm volatile("ldmatrix.sync.aligned.m8n8.x4.shared.b16 {%0,%1,%2,%3}, [%4];"
        : "=r"(r[0]), "=r"(r[1]), "=r"(r[2]), "=r"(r[3]) : "r"(addr));
}
__device__ __forceinline__ void ldm_x4_t(uint32_t* r, uint32_t addr) {
    asm volatile("ldmatrix.sync.aligned.m8n8.x4.trans.shared.b16 {%0,%1,%2,%3}, [%4];"
        : "=r"(r[0]), "=r"(r[1]), "=r"(r[2]), "=r"(r[3]) : "r"(addr));
}
__device__ __forceinline__ void mma_bf16(float* d, const uint32_t* a, uint32_t b0, uint32_t b1) {
    asm volatile(
        "mma.sync.aligned.m16n8k16.row.col.f32.bf16.bf16.f32 "
        "{%0,%1,%2,%3}, {%4,%5,%6,%7}, {%8,%9}, {%0,%1,%2,%3};"
        : "+f"(d[0]), "+f"(d[1]), "+f"(d[2]), "+f"(d[3])
        : "r"(a[0]), "r"(a[1]), "r"(a[2]), "r"(a[3]), "r"(b0), "r"(b1));
}
__device__ __forceinline__ uint32_t bf2u(float a, float b) {
    __nv_bfloat162 p = __floats2bfloat162_rn(a, b);
    return *(uint32_t*)&p;
}
__device__ __forceinline__ float qmax(float v) {
    v = fmaxf(v, __shfl_xor_sync(0xffffffffu, v, 1));
    v = fmaxf(v, __shfl_xor_sync(0xffffffffu, v, 2));
    return v;
}
__device__ __forceinline__ float qsum(float v) {
    v += __shfl_xor_sync(0xffffffffu, v, 1);
    v += __shfl_xor_sync(0xffffffffu, v, 2);
    return v;
}

// ============ K1: fused 1x1 convs -> bf16 operand layouts ============
__global__ __launch_bounds__(256) void k1_proj(
    const float* __restrict__ x,
    const float* __restrict__ wb, const float* __restrict__ bb,
    const float* __restrict__ wc, const float* __restrict__ bc,
    const float* __restrict__ wd, const float* __restrict__ bd)
{
    __shared__ __align__(16) float Ws[80*64];
    __shared__ float Bs[80];
    int t = threadIdx.x;
    for (int i = t; i < 512;  i += 256) Ws[i]        = wb[i];
    for (int i = t; i < 512;  i += 256) Ws[512 + i]  = wc[i];
    for (int i = t; i < 4096; i += 256) Ws[1024 + i] = wd[i];
    if (t < 8)        Bs[t] = bb[t];
    else if (t < 16)  Bs[t] = bc[t - 8];
    else if (t < 80)  Bs[t] = bd[t - 16];
    __syncthreads();

    int gid = blockIdx.x * 256 + t;
    int b = gid >> 12, p = gid & 4095;
    float xv[64];
    const float* xb = x + (size_t)b * Cn * Nn + p;
#pragma unroll
    for (int c = 0; c < 64; c++) xv[c] = xb[c * Nn];

    float accT[8];
    for (int o = 0; o < 80; o++) {
        float acc = Bs[o];
        const float4* wr = (const float4*)&Ws[o * 64];
#pragma unroll
        for (int c4 = 0; c4 < 16; c4++) {
            float4 w4 = wr[c4];
            acc += w4.x * xv[c4*4] + w4.y * xv[c4*4+1] + w4.z * xv[c4*4+2] + w4.w * xv[c4*4+3];
        }
        if (o < 8) {
            accT[o] = acc;
            if (o == 7) {
                uint4 v;
                v.x = bf2u(accT[0], accT[1]); v.y = bf2u(accT[2], accT[3]);
                v.z = bf2u(accT[4], accT[5]); v.w = bf2u(accT[6], accT[7]);
                *(uint4*)&g_featBT[((size_t)b * Nn + p) * 8] = v;
            }
        } else if (o < 16) {
            g_featCb[((size_t)b * 8 + (o - 8)) * Nn + p] = __float2bfloat16(acc);
        } else {
            int c = o - 16;
            accT[c & 7] = acc;
            if ((c & 7) == 7) {
                uint4 v;
                v.x = bf2u(accT[0], accT[1]); v.y = bf2u(accT[2], accT[3]);
                v.z = bf2u(accT[4], accT[5]); v.w = bf2u(accT[6], accT[7]);
                *(uint4*)&g_featDT[((size_t)b * Nn + p) * 64 + (c - 7)] = v;
            }
        }
    }
}

// ============ K2: PAM flash attention, full register pipeline (FA2) ============
#define KST2 72
#define VST2 72
__global__ __launch_bounds__(128, 4) void k2_pam(
    const float* __restrict__ x, const float* __restrict__ alpha_p)
{
    __shared__ __align__(16) __nv_bfloat16 Qb[64*16];
    __shared__ __align__(16) __nv_bfloat16 Kb[16*KST2];
    __shared__ __align__(16) __nv_bfloat16 Vb[64*VST2];

    int b = blockIdx.y, q0 = blockIdx.x * 64;
    int t = threadIdx.x, lane = t & 31, warp = t >> 5;
    int qbase = warp * 16;

    const __nv_bfloat16* featB = g_featBT + (size_t)b * Nn * 8;
    const __nv_bfloat16* featC = g_featCb + (size_t)b * 8 * Nn;
    const __nv_bfloat16* featD = g_featDT + (size_t)b * Nn * 64;

    // init: Q tile (cols 8..15 zero), Kb all-zero (rows 8..15 stay zero)
    {
        int q = t >> 1;
        if (t & 1) {
            uint4 z = {0,0,0,0};
            *(uint4*)&Qb[q * 16 + 8] = z;
        } else {
            *(uint4*)&Qb[q * 16] = *(const uint4*)&featB[(size_t)(q0 + q) * 8];
        }
        for (int i = t; i < 16 * KST2 / 8; i += 128) {
            uint4 z = {0,0,0,0};
            *(uint4*)&Kb[i * 8] = z;
        }
    }
    __syncthreads();

    // per-warp Q fragment (A, 16x16)
    uint32_t qa[4];
    {
        int r16 = lane & 15, ch = (lane >> 4) * 8;
        ldm_x4(qa, sptr(&Qb[(qbase + r16) * 16 + ch]));
    }

    // running stats in registers (rows r = lane>>2 and r+8; identical across quad)
    float m0 = -INFINITY, m1 = -INFINITY, l0 = 0.f, l1 = 0.f;
    float acc[8][4];
#pragma unroll
    for (int n = 0; n < 8; n++)
#pragma unroll
        for (int j = 0; j < 4; j++) acc[n][j] = 0.f;

    int r = lane & 7, sel = lane >> 3;

    for (int mc = 0; mc < 64; mc++) {
        int M0 = mc * 64;
        // load K chunk rows 0-7 (bf16 pairs)
        for (int i = t; i < 256; i += 128) {
            int c = i >> 5, m2 = i & 31;
            *(uint32_t*)&Kb[c * KST2 + 2 * m2] =
                *(const uint32_t*)&featC[(size_t)c * Nn + M0 + 2 * m2];
        }
        // load V chunk [m][c]: 64 rows x 8 uint4
        for (int i = t; i < 512; i += 128) {
            int m = i >> 3, cq = i & 7;
            *(uint4*)&Vb[m * VST2 + cq * 8] =
                *(const uint4*)&featD[(size_t)(M0 + m) * 64 + cq * 8];
        }
        __syncthreads();

        // ---- scores in registers: sA = row r, sB = row r+8 (16 cols each) ----
        float sA[16], sB[16];
#pragma unroll
        for (int nt2 = 0; nt2 < 4; nt2++) {
            uint32_t kb[4];
            ldm_x4_t(kb, sptr(&Kb[(r + (sel & 1) * 8) * KST2 + nt2 * 16 + (sel >> 1) * 8]));
            float d0[4] = {0,0,0,0}, d1[4] = {0,0,0,0};
            mma_bf16(d0, qa, kb[0], kb[1]);
            mma_bf16(d1, qa, kb[2], kb[3]);
            sA[nt2*4+0] = d0[0]; sA[nt2*4+1] = d0[1];
            sA[nt2*4+2] = d1[0]; sA[nt2*4+3] = d1[1];
            sB[nt2*4+0] = d0[2]; sB[nt2*4+1] = d0[3];
            sB[nt2*4+2] = d1[2]; sB[nt2*4+3] = d1[3];
        }

        // ---- online softmax in registers (quad shuffles) ----
        float cmA = sA[0], cmB = sB[0];
#pragma unroll
        for (int i = 1; i < 16; i++) { cmA = fmaxf(cmA, sA[i]); cmB = fmaxf(cmB, sB[i]); }
        cmA = qmax(cmA); cmB = qmax(cmB);
        float nmA = fmaxf(m0, cmA), nmB = fmaxf(m1, cmB);
        float scA = __expf(m0 - nmA), scB = __expf(m1 - nmB);
        m0 = nmA; m1 = nmB;
        float sumA = 0.f, sumB = 0.f;
#pragma unroll
        for (int i = 0; i < 16; i++) {
            sA[i] = __expf(sA[i] - nmA); sumA += sA[i];
            sB[i] = __expf(sB[i] - nmB); sumB += sB[i];
        }
        sumA = qsum(sumA); sumB = qsum(sumB);
        l0 = l0 * scA + sumA;
        l1 = l1 * scB + sumB;

        // ---- rescale acc, build P A-fragments directly from prob registers ----
#pragma unroll
        for (int n = 0; n < 8; n++) {
            acc[n][0] *= scA; acc[n][1] *= scA;
            acc[n][2] *= scB; acc[n][3] *= scB;
        }
        uint32_t pa[4][4];
#pragma unroll
        for (int kt = 0; kt < 4; kt++) {
            pa[kt][0] = bf2u(sA[kt*4+0], sA[kt*4+1]);
            pa[kt][1] = bf2u(sB[kt*4+0], sB[kt*4+1]);
            pa[kt][2] = bf2u(sA[kt*4+2], sA[kt*4+3]);
            pa[kt][3] = bf2u(sB[kt*4+2], sB[kt*4+3]);
        }

        // ---- P·V accumulate ----
#pragma unroll
        for (int kt = 0; kt < 4; kt++) {
#pragma unroll
            for (int nt2 = 0; nt2 < 4; nt2++) {
                uint32_t vb[4];
                ldm_x4_t(vb, sptr(&Vb[(kt * 16 + r + (sel & 1) * 8) * VST2
                                      + nt2 * 16 + (sel >> 1) * 8]));
                mma_bf16(acc[nt2 * 2],     pa[kt], vb[0], vb[1]);
                mma_bf16(acc[nt2 * 2 + 1], pa[kt], vb[2], vb[3]);
            }
        }
        __syncthreads();
    }

    // epilogue: normalize + alpha residual
    {
        float alpha = *alpha_p;
        int row = lane >> 2, col2 = (lane & 3) * 2;
        float il0 = 1.f / l0;
        float il1 = 1.f / l1;
        int qA = q0 + qbase + row;
#pragma unroll
        for (int nt = 0; nt < 8; nt++) {
            int c = nt * 8 + col2;
            size_t o0 = ((size_t)b * Cn + c) * Nn + qA;
            g_x1[o0]          = alpha * acc[nt][0] * il0 + x[o0];
            g_x1[o0 + Nn]     = alpha * acc[nt][1] * il0 + x[o0 + Nn];
            g_x1[o0 + 8]      = alpha * acc[nt][2] * il1 + x[o0 + 8];
            g_x1[o0 + Nn + 8] = alpha * acc[nt][3] * il1 + x[o0 + Nn + 8];
        }
    }
}

// ============ K3a: CAM Gram partials (split over N) ============
__global__ __launch_bounds__(256) void k3a_gram()
{
    __shared__ float Xs[64 * 129];
    int b = blockIdx.y, ns = blockIdx.x;
    int n0 = ns * 128;
    int t = threadIdx.x;
    const float* x1b = g_x1 + (size_t)b * Cn * Nn;
    for (int idx = t; idx < 64 * 128; idx += 256) {
        int c = idx >> 7, n = idx & 127;
        Xs[c * 129 + n] = x1b[c * Nn + n0 + n];
    }
    __syncthreads();
    int c0 = t & 63, dg = t >> 6;
    float acc[16];
#pragma unroll
    for (int k = 0; k < 16; k++) acc[k] = 0.f;
    for (int n = 0; n < 128; n++) {
        float xc = Xs[c0 * 129 + n];
#pragma unroll
        for (int k = 0; k < 16; k++) acc[k] += xc * Xs[(dg * 16 + k) * 129 + n];
    }
#pragma unroll
    for (int k = 0; k < 16; k++)
        g_gram[(((size_t)ns * Bn + b) * Cn + c0) * Cn + dg * 16 + k] = acc[k];
}

// ============ K3b: CAM softmax(max-att) ============
__global__ __launch_bounds__(64) void k3b_soft()
{
    int c = blockIdx.x, b = blockIdx.y, d = threadIdx.x;
    float v = 0.f;
    for (int ns = 0; ns < 32; ns++)
        v += g_gram[(((size_t)ns * Bn + b) * Cn + c) * Cn + d];
    __shared__ float vals[64], pbuf[64];
    vals[d] = v;
    __syncthreads();
    float mn = INFINITY;
    for (int i = 0; i < 64; i++) mn = fminf(mn, vals[i]);
    float p = __expf(mn - v);
    pbuf[d] = p;
    __syncthreads();
    float S = 0.f;
    for (int i = 0; i < 64; i++) S += pbuf[i];
    g_Pmat[((size_t)b * Cn + c) * Cn + d] = p / S;
}

// ============ K3c: CAM apply + beta residual ============
__global__ __launch_bounds__(256) void k3c_apply(const float* __restrict__ beta_p)
{
    __shared__ __align__(16) float Pm[4096];
    int b = blockIdx.y;
    int t = threadIdx.x;
    for (int i = t; i < 4096; i += 256) Pm[i] = g_Pmat[(size_t)b * 4096 + i];
    __syncthreads();
    int p = blockIdx.x * 256 + t;
    float xv[64];
    const float* x1b = g_x1 + (size_t)b * Cn * Nn + p;
#pragma unroll
    for (int c = 0; c < 64; c++) xv[c] = x1b[c * Nn];
    float beta = *beta_p;
    for (int c = 0; c < 64; c++) {
        float acc = 0.f;
        const float4* pr = (const float4*)&Pm[c * 64];
#pragma unroll
        for (int d4 = 0; d4 < 16; d4++) {
            float4 w4 = pr[d4];
            acc += w4.x * xv[d4*4] + w4.y * xv[d4*4+1] + w4.z * xv[d4*4+2] + w4.w * xv[d4*4+3];
        }
        g_x2[((size_t)b * Cn + c) * Nn + p] = beta * acc + xv[c];
    }
}

// ============ K4: conv3x3 (pad 1) -> g_conv (with bias) ============
__global__ __launch_bounds__(256) void k4_conv(
    const float* __restrict__ w, const float* __restrict__ bias)
{
    __shared__ float In[8][18][18];
    __shared__ __align__(16) float Ws[32][8][12];
    int b = blockIdx.z, ocg = blockIdx.y, tile = blockIdx.x;
    int ty0 = (tile >> 2) * 16, tx0 = (tile & 3) * 16;
    int t = threadIdx.x;
    int lx = t & 15, ly = t >> 4;
    float acc[32];
#pragma unroll
    for (int oc = 0; oc < 32; oc++) acc[oc] = bias[ocg * 32 + oc];
    const float* xin = g_x2 + (size_t)b * Cn * Nn;

    for (int icc = 0; icc < 8; icc++) {
        __syncthreads();
        for (int idx = t; idx < 2592; idx += 256) {
            int ic = idx / 324;
            int rem = idx - ic * 324;
            int r = rem / 18, cc = rem - r * 18;
            int y = ty0 + r - 1, xx = tx0 + cc - 1;
            float v = 0.f;
            if (y >= 0 && y < 64 && xx >= 0 && xx < 64)
                v = xin[(icc * 8 + ic) * Nn + y * 64 + xx];
            In[ic][r][cc] = v;
        }
        for (int idx = t; idx < 32 * 8 * 9; idx += 256) {
            int oc = idx / 72;
            int rem = idx - oc * 72;
            int ic = rem / 9, k = rem - ic * 9;
            Ws[oc][ic][k] = w[(((size_t)(ocg * 32 + oc)) * 64 + icc * 8 + ic) * 9 + k];
        }
        __syncthreads();
#pragma unroll
        for (int ic = 0; ic < 8; ic++) {
            float i0 = In[ic][ly    ][lx], i1 = In[ic][ly    ][lx+1], i2 = In[ic][ly    ][lx+2];
            float i3 = In[ic][ly + 1][lx], i4 = In[ic][ly + 1][lx+1], i5 = In[ic][ly + 1][lx+2];
            float i6 = In[ic][ly + 2][lx], i7 = In[ic][ly + 2][lx+1], i8 = In[ic][ly + 2][lx+2];
#pragma unroll
            for (int oc = 0; oc < 32; oc++) {
                float4 wa = *(const float4*)&Ws[oc][ic][0];
                float4 wb = *(const float4*)&Ws[oc][ic][4];
                float w8 = Ws[oc][ic][8];
                acc[oc] += i0*wa.x + i1*wa.y + i2*wa.z + i3*wa.w
                         + i4*wb.x + i5*wb.y + i6*wb.z + i7*wb.w + i8*w8;
            }
        }
    }
#pragma unroll
    for (int oc = 0; oc < 32; oc++)
        g_conv[((size_t)b * 128 + ocg * 32 + oc) * Nn + (ty0 + ly) * 64 + tx0 + lx] = acc[oc];
}

// ============ K5: BN batch stats (deterministic, 1 block/channel) ============
__global__ __launch_bounds__(256) void k5_bnstats(
    const float* __restrict__ gamma, const float* __restrict__ betab)
{
    int c = blockIdx.x, t = threadIdx.x;
    float s = 0.f, s2 = 0.f;
    for (int i = t; i < Bn * Nn; i += 256) {
        int bb = i >> 12, p = i & 4095;
        float v = g_conv[((size_t)bb * 128 + c) * Nn + p];
        s += v; s2 += v * v;
    }
    __shared__ float rs[256], rq[256];
    rs[t] = s; rq[t] = s2;
    __syncthreads();
    for (int o = 128; o > 0; o >>= 1) {
        if (t < o) { rs[t] += rs[t + o]; rq[t] += rq[t + o]; }
        __syncthreads();
    }
    if (t == 0) {
        float mean = rs[0] / 32768.f;
        float var = rq[0] / 32768.f - mean * mean;
        float sc = gamma[c] * rsqrtf(var + 1e-5f);
        g_bnscale[c] = sc;
        g_bnshift[c] = betab[c] - mean * sc;
    }
}

// ============ K6: BN apply + ReLU + maxpool(2,2, h-pad (1,1)) ============
__global__ __launch_bounds__(256) void k6_pool(float* __restrict__ out)
{
    int idx = blockIdx.x * 256 + threadIdx.x;
    const int TOT = Bn * 128 * 33 * 32;
    if (idx >= TOT) return;
    int ow = idx & 31;
    int rest = idx >> 5;
    int oh = rest % 33; rest /= 33;
    int c = rest & 127;
    int b = rest >> 7;
    float sc = g_bnscale[c], sh = g_bnshift[c];
    const float* base = g_conv + ((size_t)b * 128 + c) * Nn;
    int r0 = 2 * oh - 1, r1 = 2 * oh;
    int x0 = 2 * ow;
    float m = -INFINITY;
    if (r0 >= 0 && r0 < 64) {
        m = fmaxf(m, fmaxf(base[r0 * 64 + x0] * sc + sh, 0.f));
        m = fmaxf(m, fmaxf(base[r0 * 64 + x0 + 1] * sc + sh, 0.f));
    }
    if (r1 < 64) {
        m = fmaxf(m, fmaxf(base[r1 * 64 + x0] * sc + sh, 0.f));
        m = fmaxf(m, fmaxf(base[r1 * 64 + x0 + 1] * sc + sh, 0.f));
    }
    out[idx] = m;
}

// ---------------- launch ----------------
extern "C" void kernel_launch(void* const* d_in, const int* in_sizes, int n_in,
                              void* d_out, int out_size)
{
    const float* x       = (const float*)d_in[0];
    const float* conv_bw = (const float*)d_in[1];
    const float* conv_bb = (const float*)d_in[2];
    const float* conv_cw = (const float*)d_in[3];
    const float* conv_cb = (const float*)d_in[4];
    const float* conv_dw = (const float*)d_in[5];
    const float* conv_db = (const float*)d_in[6];
    const float* alpha   = (const float*)d_in[7];
    const float* beta    = (const float*)d_in[8];
    const float* conv_w  = (const float*)d_in[9];
    const float* conv_b  = (const float*)d_in[10];
    const float* bn_g    = (const float*)d_in[11];
    const float* bn_b    = (const float*)d_in[12];
    float* out = (float*)d_out;

    k1_proj<<<128, 256>>>(x, conv_bw, conv_bb, conv_cw, conv_cb, conv_dw, conv_db);
    k2_pam<<<dim3(64, Bn), 128>>>(x, alpha);
    k3a_gram<<<dim3(32, Bn), 256>>>();
    k3b_soft<<<dim3(64, Bn), 64>>>();
    k3c_apply<<<dim3(16, Bn), 256>>>(beta);
    k4_conv<<<dim3(16, 4, Bn), 256>>>(conv_w, conv_b);
    k5_bnstats<<<128, 256>>>(bn_g, bn_b);
    k6_pool<<<4224, 256>>>(out);
}